// round 16
// baseline (speedup 1.0000x reference)
#include <cuda_runtime.h>
#include <cuda_bf16.h>
#include <cstdint>

// ---------------------------------------------------------------------------
// RnnTfModel: k_embproj (R1 numerics, gate-interleaved output) + fused LSTM.
// R16 = R15 + gate-packed float4 partials:
//   matvec thread owns gate-strided cols {jq,64+jq,128+jq,192+jq} -> its 4
//   accs are (i,f,g,o) of one unit -> 1 float4 store/row; combine reads
//   8 LDS.128 (not 32 LDS.32) and reduces with add.f32x2. g_table is
//   gate-interleaved so xz prefetch is 1 LDG.128. Numerics order-identical.
// B=512, T=1024, D=H=64, 4H=256, V=8193. 128 blocks x 512 threads.
// ---------------------------------------------------------------------------

#define B_   512
#define T_   1024
#define D_   64
#define G4_  256
#define V_   8193
#define NB_  4
#define NBLK_ 128
#define THR_ 512

using ull = unsigned long long;

__device__ float g_table[V_ * G4_];   // [v][u][gate] gate-interleaved, 8.4 MB

__device__ __forceinline__ void ffma2(ull& d, ull a, ull b) {
    asm("fma.rn.f32x2 %0, %1, %2, %0;" : "+l"(d) : "l"(a), "l"(b));
}
__device__ __forceinline__ void add2(ull& d, ull a) {
    asm("add.rn.f32x2 %0, %0, %1;" : "+l"(d) : "l"(a));
}
__device__ __forceinline__ float2 unpack2(ull v) {
    float2 f;
    asm("mov.b64 {%0, %1}, %2;" : "=f"(f.x), "=f"(f.y) : "l"(v));
    return f;
}
__device__ __forceinline__ ull pack2(float lo, float hi) {
    ull v;
    asm("mov.b64 %0, {%1, %2};" : "=l"(v) : "f"(lo), "f"(hi));
    return v;
}
__device__ __forceinline__ float sigm_(float x) {
    return 1.0f / (1.0f + __expf(-x));
}
__device__ __forceinline__ float tanh_(float x) {
    float e = __expf(-2.0f * x);
    return (1.0f - e) / (1.0f + e);
}

// ---------------------------------------------------------------------------
// Kernel 1: projected embedding table — R1 accumulation order, but output is
// gate-interleaved: g_table[v*256 + u*4 + g] for gate column j = g*64+u.
// ---------------------------------------------------------------------------
__global__ void k_embproj(const float* __restrict__ emb,
                          const float* __restrict__ W1,
                          const float* __restrict__ b1) {
    int v = blockIdx.x;
    int j = threadIdx.x;
    __shared__ float e[D_];
    if (j < D_) e[j] = emb[v * D_ + j];
    __syncthreads();
    float acc = b1[j];
#pragma unroll
    for (int k = 0; k < D_; k++) acc += e[k] * __ldg(&W1[k * G4_ + j]);
    int g = j >> 6, u = j & 63;
    g_table[v * G4_ + u * 4 + g] = acc;
}

// ---------------------------------------------------------------------------
// Kernel 2: fused LSTM + head, 512 threads.
// matvec role: thread (ke = j>>6 in [0,8), jq = j&63) owns gate-strided cols
//   {jq, 64+jq, 128+jq, 192+jq}:
//   z2: stacked [h1_t; h2_{t-1}] rows [16ke,16ke+16);  z1: U1 rows [8ke,8ke+8).
//   Partials: ONE float4 (i,f,g,o) per batch row -> zp[ke][r][jq] (float4).
// combine role: lay = j>>8 (0: h2_t, 1: h1_{t+1}), rc=(j>>6)&3, uc=j&63.
// Dynamic smem (floats):
//   [0,512) hc1[2][4][64]; [512,1024) hc2[2][4][64];
//   [1024,9216) zp1[8][4][64]xfloat4; [9216,17408) zp2 same;
//   [17408,21504) code_s; [21504,21768) zbn; [21768,21896) hid
// ---------------------------------------------------------------------------
#define SM_HC1   0
#define SM_HC2   512
#define SM_ZP1   1024
#define SM_ZP2   9216
#define SM_CODE  17408
#define SM_ZBN   21504
#define SM_HID   21768
#define SMEM_BYTES (21896 * 4)

__global__ void __launch_bounds__(THR_, 1)
k_main(const int* __restrict__ code_in,
       const float* __restrict__ U1,
       const float* __restrict__ W2,
       const float* __restrict__ U2,
       const float* __restrict__ b2,
       const float* __restrict__ aux,
       const float* __restrict__ Wlm, const float* __restrict__ blm,
       const float* __restrict__ gamma, const float* __restrict__ beta,
       const float* __restrict__ mean, const float* __restrict__ var,
       const float* __restrict__ W3, const float* __restrict__ b3,
       const float* __restrict__ W4, const float* __restrict__ b4,
       float* __restrict__ out) {
    extern __shared__ __align__(16) float smem[];
    float* hc1   = smem + SM_HC1;
    float* hc2   = smem + SM_HC2;
    float* zp1   = smem + SM_ZP1;    // float4 at (q*256 + r*64 + jq)*4
    float* zp2   = smem + SM_ZP2;
    int*   code_s = (int*)(smem + SM_CODE);
    float* zbn   = smem + SM_ZBN;
    float* hid   = smem + SM_HID;

    const int j   = threadIdx.x;
    const int ke  = j >> 6;          // k-eighth (warp-uniform)
    const int jq  = j & 63;          // owned unit (gate-strided cols)
    const int lay = j >> 8;          // combine layer: 0 -> h2, 1 -> h1
    const int rc  = (j >> 6) & 3;    // combine row
    const int uc  = j & 63;          // combine unit
    const int b0  = blockIdx.x * NB_;

    // ---- z2 weights: stacked [W2;U2] rows [16ke,16ke+16), gate-strided ----
    const float* M2 = (ke < 4) ? W2 : U2;
    const int kr0 = 16 * (ke & 3);
    ull w2[4][8];
#pragma unroll
    for (int c = 0; c < 4; c++)
#pragma unroll
        for (int p = 0; p < 8; p++) {
            int k = kr0 + 2 * p;
            w2[c][p] = pack2(__ldg(&M2[k * G4_ + 64 * c + jq]),
                             __ldg(&M2[(k + 1) * G4_ + 64 * c + jq]));
        }
    // ---- z1 weights: U1 rows [8ke,8ke+8), gate-strided cols ----
    ull w1[4][4];
#pragma unroll
    for (int c = 0; c < 4; c++)
#pragma unroll
        for (int p = 0; p < 4; p++) {
            int k = 8 * ke + 2 * p;
            w1[c][p] = pack2(__ldg(&U1[k * G4_ + 64 * c + jq]),
                             __ldg(&U1[(k + 1) * G4_ + 64 * c + jq]));
        }

    // combine-role constants: packed (b_i,b_f),(b_g,b_o) for unit uc
    ull bias0 = 0, bias1 = 0;
    if (lay == 0) {
        bias0 = pack2(__ldg(&b2[uc]), __ldg(&b2[64 + uc]));
        bias1 = pack2(__ldg(&b2[128 + uc]), __ldg(&b2[192 + uc]));
    }

    for (int i = j; i < NB_ * T_; i += THR_) {
        int r = i >> 10, t = i & (T_ - 1);
        code_s[i] = code_in[(b0 + r) * T_ + t];
    }
    hc1[j] = 0.0f;
    hc2[j] = 0.0f;
    __syncthreads();

    float c1 = 0.0f, c2 = 0.0f;
    ulonglong2 cur;
    cur.x = 0; cur.y = 0;

    // ---- prologue (lay==1): h1_0 = f(x_0); cur = x_1 ----
    if (lay == 1) {
        const float4 x0 = *(const float4*)
            &g_table[(size_t)code_s[rc * T_] * G4_ + uc * 4];
        float iv = sigm_(x0.x);
        float gv = tanh_(x0.z);
        float ov = sigm_(x0.w);
        c1 = iv * gv;
        hc1[0 * 256 + rc * 64 + uc] = ov * tanh_(c1);   // buf1[0] = h1_0
        cur = *(const ulonglong2*)
            &g_table[(size_t)code_s[rc * T_ + 1] * G4_ + uc * 4];
    }
    __syncthreads();   // h1_0 visible

    // ============================ LSTM loop ================================
    for (int t = 0; t < T_; t++) {
        const int ca = t & 1, cb = (t + 1) & 1;

        ulonglong2 nxt;
        nxt.x = 0; nxt.y = 0;
        if (lay == 1) {                  // prefetch x_{t+2} (clamped)
            int tn = (t + 2 < T_) ? (t + 2) : (T_ - 1);
            nxt = *(const ulonglong2*)
                &g_table[(size_t)code_s[rc * T_ + tn] * G4_ + uc * 4];
        }

        const float* h1b = &hc1[ca * 256];   // h1_t
        const float* h2b = &hc2[cb * 256];   // h2_{t-1}
        const float* kb  = (ke < 4) ? h1b : h2b;

        // ---- z2(t) partials: this thread's 16 stacked k-rows ----
#pragma unroll
        for (int r = 0; r < NB_; r++) {
            ull acc[4] = {0, 0, 0, 0};
#pragma unroll
            for (int i = 0; i < 4; i++) {
                ulonglong2 hv = *(const ulonglong2*)&kb[r * 64 + kr0 + 4 * i];
#pragma unroll
                for (int c = 0; c < 4; c++) {
                    ffma2(acc[c], hv.x, w2[c][2 * i]);
                    ffma2(acc[c], hv.y, w2[c][2 * i + 1]);
                }
            }
            float2 p0 = unpack2(acc[0]), p1 = unpack2(acc[1]);
            float2 p2 = unpack2(acc[2]), p3 = unpack2(acc[3]);
            *(float4*)&zp2[(ke * 256 + r * 64 + jq) * 4] =
                make_float4(p0.x + p0.y, p1.x + p1.y,
                            p2.x + p2.y, p3.x + p3.y);
        }
        // ---- z1(t+1) partials: this thread's 8 U1 k-rows vs h1_t ----
#pragma unroll
        for (int r = 0; r < NB_; r++) {
            ull acc[4] = {0, 0, 0, 0};
#pragma unroll
            for (int i = 0; i < 2; i++) {
                ulonglong2 hv = *(const ulonglong2*)
                    &h1b[r * 64 + 8 * ke + 4 * i];
#pragma unroll
                for (int c = 0; c < 4; c++) {
                    ffma2(acc[c], hv.x, w1[c][2 * i]);
                    ffma2(acc[c], hv.y, w1[c][2 * i + 1]);
                }
            }
            float2 p0 = unpack2(acc[0]), p1 = unpack2(acc[1]);
            float2 p2 = unpack2(acc[2]), p3 = unpack2(acc[3]);
            *(float4*)&zp1[(ke * 256 + r * 64 + jq) * 4] =
                make_float4(p0.x + p0.y, p1.x + p1.y,
                            p2.x + p2.y, p3.x + p3.y);
        }
        __syncthreads();   // S_a: zp1, zp2 ready

        // ---- combine, split by layer across thread halves ----
        if (lay == 0) {
            // h2_t for (rc, uc): acc = bias + sum_q zp2[q]
            ull a0 = bias0, a1 = bias1;
#pragma unroll
            for (int q = 0; q < 8; q++) {
                ulonglong2 v = *(const ulonglong2*)
                    &zp2[(q * 256 + rc * 64 + uc) * 4];
                add2(a0, v.x);
                add2(a1, v.y);
            }
            float2 pif = unpack2(a0), pgo = unpack2(a1);
            float iv = sigm_(pif.x), fv = sigm_(pif.y);
            float gv = tanh_(pgo.x), ov = sigm_(pgo.y);
            c2 = fv * c2 + iv * gv;
            hc2[ca * 256 + rc * 64 + uc] = ov * tanh_(c2);
        } else {
            // h1_{t+1} for (rc, uc): acc = x_{t+1} + sum_q zp1[q]
            ull a0 = cur.x, a1 = cur.y;
#pragma unroll
            for (int q = 0; q < 8; q++) {
                ulonglong2 v = *(const ulonglong2*)
                    &zp1[(q * 256 + rc * 64 + uc) * 4];
                add2(a0, v.x);
                add2(a1, v.y);
            }
            float2 pif = unpack2(a0), pgo = unpack2(a1);
            float iv = sigm_(pif.x), fv = sigm_(pif.y);
            float gv = tanh_(pgo.x), ov = sigm_(pgo.y);
            c1 = fv * c1 + iv * gv;
            hc1[cb * 256 + rc * 64 + uc] = ov * tanh_(c1);
            cur = nxt;
        }
        __syncthreads();   // S_b: new h states visible
    }

    // final h2 = hc2[1]  (last write: t=1023, ca=1)
    // ============================ head (4 rows) ============================
    if (j < 264) {
        int r = j / 66, k = j % 66;
        float v = (k < 2) ? aux[(b0 + r) * 2 + k]
                          : hc2[1 * 256 + r * 64 + (k - 2)];
        zbn[r * 66 + k] =
            gamma[k] * (v - mean[k]) * rsqrtf(var[k] + 1e-3f) + beta[k];
    }
    __syncthreads();
    if (j < 128) {
        int r = j >> 5, i = j & 31;
        float acc = b3[i];
#pragma unroll
        for (int k = 0; k < 66; k++)
            acc += zbn[r * 66 + k] * __ldg(&W3[k * 32 + i]);
        hid[r * 32 + i] = fmaxf(acc, 0.0f);
    }
    __syncthreads();
    if (j < NB_) {
        int r = j;
        float o0 = b4[0], o1 = b4[1];
#pragma unroll
        for (int k = 0; k < 32; k++) {
            o0 += hid[r * 32 + k] * __ldg(&W4[k * 2 + 0]);
            o1 += hid[r * 32 + k] * __ldg(&W4[k * 2 + 1]);
        }
        float m = fmaxf(o0, o1);
        float e0 = __expf(o0 - m), e1 = __expf(o1 - m);
        float inv = 1.0f / (e0 + e1);
        out[(b0 + r) * 2 + 0] = e0 * inv;
        out[(b0 + r) * 2 + 1] = e1 * inv;

        float l0 = blm[0], l1 = blm[1];
#pragma unroll
        for (int k = 0; k < 64; k++) {
            float h = hc2[1 * 256 + r * 64 + k];
            l0 += h * __ldg(&Wlm[k * 2 + 0]);
            l1 += h * __ldg(&Wlm[k * 2 + 1]);
        }
        out[B_ * 2 + (b0 + r) * 2 + 0] = sigm_(l0);
        out[B_ * 2 + (b0 + r) * 2 + 1] = sigm_(l1);
    }
}

// ---------------------------------------------------------------------------
// launcher
// inputs: 0 aux_in, 1 code_in, 2 emb, 3 W1, 4 U1, 5 b1, 6 W2, 7 U2, 8 b2,
//         9 Wlm, 10 blm, 11 bn_gamma, 12 bn_beta, 13 bn_mean, 14 bn_var,
//         15 W3, 16 b3, 17 W4, 18 b4
// ---------------------------------------------------------------------------
extern "C" void kernel_launch(void* const* d_in, const int* in_sizes, int n_in,
                              void* d_out, int out_size) {
    const float* aux   = (const float*)d_in[0];
    const int*   code  = (const int*)d_in[1];
    const float* emb   = (const float*)d_in[2];
    const float* W1    = (const float*)d_in[3];
    const float* U1    = (const float*)d_in[4];
    const float* b1    = (const float*)d_in[5];
    const float* W2    = (const float*)d_in[6];
    const float* U2    = (const float*)d_in[7];
    const float* b2    = (const float*)d_in[8];
    const float* Wlm   = (const float*)d_in[9];
    const float* blm   = (const float*)d_in[10];
    const float* gamma = (const float*)d_in[11];
    const float* beta  = (const float*)d_in[12];
    const float* mean  = (const float*)d_in[13];
    const float* var   = (const float*)d_in[14];
    const float* W3    = (const float*)d_in[15];
    const float* b3    = (const float*)d_in[16];
    const float* W4    = (const float*)d_in[17];
    const float* b4    = (const float*)d_in[18];
    float* out = (float*)d_out;

    cudaFuncSetAttribute(k_main, cudaFuncAttributeMaxDynamicSharedMemorySize,
                         SMEM_BYTES);

    k_embproj<<<V_, 256>>>(emb, W1, b1);
    k_main<<<NBLK_, THR_, SMEM_BYTES>>>(code, U1, W2, U2, b2,
                                        aux, Wlm, blm, gamma, beta, mean, var,
                                        W3, b3, W4, b4, out);
}